// round 4
// baseline (speedup 1.0000x reference)
#include <cuda_runtime.h>

// out[b, i, p] = W[i, b] * params[p, b]
// params: [P=512, B=512] row-major (params[p*512 + b])
// W:      [I=512, B=512] row-major (W[i*512 + b])
// out:    [B=512, I=512, P=512] row-major
//
// One block per b. Stage column b of params and W into shared memory
// (the only strided accesses), then emit 512*512 fp32 = 1MB of coalesced
// float4 streaming stores per block. Pure HBM-write-bound.

#define NDIM 512

__global__ __launch_bounds__(512, 2)
void outer_scale_kernel(const float* __restrict__ params,
                        const float* __restrict__ W,
                        float* __restrict__ out) {
    __shared__ float pcol[NDIM];
    __shared__ float wcol[NDIM];

    const int b = blockIdx.x;
    const int t = threadIdx.x;  // 512 threads

    // Stage column b (stride-512 reads; 2 x 512 sectors per block, L2-friendly)
    pcol[t] = __ldg(&params[t * NDIM + b]);
    wcol[t] = __ldg(&W[t * NDIM + b]);
    __syncthreads();

    float4* out4 = reinterpret_cast<float4*>(out) + (size_t)b * (NDIM * NDIM / 4);
    const float4* p4 = reinterpret_cast<const float4*>(pcol);

    // 512 rows (i) x 128 float4 (p) = 65536 float4 per block; 128 iters/thread.
    // Within a warp all lanes share the same row i -> wcol[i] is an LDS broadcast.
#pragma unroll 4
    for (int idx = t; idx < NDIM * (NDIM / 4); idx += 512) {
        const int i  = idx >> 7;        // row
        const float w = wcol[i];
        float4 v = p4[idx & 127];
        v.x *= w; v.y *= w; v.z *= w; v.w *= w;
        __stcs(&out4[idx], v);          // streaming store: write-once data
    }
}

extern "C" void kernel_launch(void* const* d_in, const int* in_sizes, int n_in,
                              void* d_out, int out_size) {
    const float* params = (const float*)d_in[0];
    const float* W      = (const float*)d_in[1];
    float* out          = (float*)d_out;

    outer_scale_kernel<<<NDIM, 512>>>(params, W, out);
}